// round 10
// baseline (speedup 1.0000x reference)
#include <cuda_runtime.h>
#include <math_constants.h>

#define NQ   16384
#define NPIX 3600
#define ND   131072
#define DDIM 500
#define DP   512   // padded K
#define TOPK 8
#define CAP  16    // pass-1 candidate capture width

// Scratch (allocation-free rule: __device__ globals)
__device__ float g_query[(size_t)NQ * DP];   // emulated ref query, zero-padded [500,512)
__device__ float g_dict[(size_t)ND * DP];    // zero-padded
__device__ float g_xn_emu[ND];               // emulated fp32 ||d||^2 (XLA warp-strided)
__device__ float g_xnh[ND];                  // 0.5*xn for pass-1 scores
__device__ float g_mean32[NQ];               // fp32 row means
__device__ int   g_cand[(size_t)NQ * CAP];   // pass-1 candidates

// ---------------- K0: row means (fp64 accumulate, fp32 result) ----------------
__global__ void rowmean_kernel(const float* __restrict__ E) {
    int row = blockIdx.x;
    const float* r = E + (size_t)row * NPIX;
    double s = 0.0;
    for (int i = threadIdx.x; i < NPIX; i += 256) s += (double)r[i];
    __shared__ double sh[8];
    #pragma unroll
    for (int o = 16; o; o >>= 1) s += __shfl_down_sync(0xffffffffu, s, o);
    if ((threadIdx.x & 31) == 0) sh[threadIdx.x >> 5] = s;
    __syncthreads();
    if (threadIdx.x == 0) {
        double t = 0.0;
        #pragma unroll
        for (int w = 0; w < 8; w++) t += sh[w];
        g_mean32[row] = __fdiv_rn((float)t, (float)NPIX);
    }
}

// ---- K1: pad dictionary + emulated fp32 norms (XLA-style warp-strided) ----
// One warp per dict row: lane partial over k = lane, lane+32, ... (ascending),
// acc = fl32(acc + fl32(d*d)); then shuffle-down tree 16..1.
__global__ void dictprep_kernel(const float* __restrict__ Dm) {
    int row = blockIdx.x * 4 + (threadIdx.x >> 5);
    int lane = threadIdx.x & 31;
    const float* src = Dm + (size_t)row * DDIM;
    float* dst = g_dict + (size_t)row * DP;
    float s = 0.f;
    #pragma unroll
    for (int u = 0; u < 16; u++) {
        int j = lane + u * 32;
        float v = (j < DDIM) ? src[j] : 0.f;
        dst[j] = v;
        if (j < DDIM) s = __fadd_rn(s, __fmul_rn(v, v));
    }
    #pragma unroll
    for (int o = 16; o; o >>= 1)
        s = __fadd_rn(s, __shfl_down_sync(0xffffffffu, s, o));
    if (lane == 0) {
        g_xn_emu[row] = s;
        g_xnh[row] = 0.5f * s;   // exact scaling; pass-1 only
    }
}

// ---- K2: emulated query GEMM: q[j] = sum_k fl32(E-mean) * P, sequential k ----
// 4 queries per block, 512 threads. Thread j<500 owns output column j for all
// 4 queries and accumulates with a single fp32 accumulator over ascending k
// (cuBLAS sgemm emulation). Centered rows staged in dynamic smem as float4.
__global__ void __launch_bounds__(512) queryemu_kernel(const float* __restrict__ E,
                                                       const float* __restrict__ P) {
    extern __shared__ float4 cs4[];   // [NPIX] : (q0,q1,q2,q3) centered at k
    int qb = blockIdx.x * 4;
    int t = threadIdx.x;
    float m0 = g_mean32[qb + 0], m1 = g_mean32[qb + 1];
    float m2 = g_mean32[qb + 2], m3 = g_mean32[qb + 3];
    for (int k = t; k < NPIX; k += 512) {
        cs4[k] = make_float4(
            __fsub_rn(E[(size_t)(qb + 0) * NPIX + k], m0),
            __fsub_rn(E[(size_t)(qb + 1) * NPIX + k], m1),
            __fsub_rn(E[(size_t)(qb + 2) * NPIX + k], m2),
            __fsub_rn(E[(size_t)(qb + 3) * NPIX + k], m3));
    }
    __syncthreads();
    if (t < DDIM) {
        float a0 = 0.f, a1 = 0.f, a2 = 0.f, a3 = 0.f;
        const float* p = P + t;
        for (int k = 0; k < NPIX; k++) {
            float4 c = cs4[k];
            float pv = p[(size_t)k * DDIM];
            a0 = __fmaf_rn(c.x, pv, a0);
            a1 = __fmaf_rn(c.y, pv, a1);
            a2 = __fmaf_rn(c.z, pv, a2);
            a3 = __fmaf_rn(c.w, pv, a3);
        }
        g_query[(size_t)(qb + 0) * DP + t] = a0;
        g_query[(size_t)(qb + 1) * DP + t] = a1;
        g_query[(size_t)(qb + 2) * DP + t] = a2;
        g_query[(size_t)(qb + 3) * DP + t] = a3;
    } else {
        // zero the pad columns [500,512)
        #pragma unroll
        for (int q4 = 0; q4 < 4; q4++)
            g_query[(size_t)(qb + q4) * DP + t] = 0.f;
    }
}

// ---------------- K3: fused distance GEMM + top-16 candidate capture ----------
__global__ void __launch_bounds__(256) knn_kernel() {
    __shared__ float As[16][64 + 4];
    __shared__ float Bs[16][128 + 4];
    __shared__ float Ssc[64][129];
    int qb = blockIdx.x * 64;
    int t = threadIdx.x;
    int tx = t & 15, ty = t >> 4;

    float ts[CAP];
    int   ti[CAP];
    #pragma unroll
    for (int r = 0; r < CAP; r++) { ts[r] = -CUDART_INF_F; ti[r] = 0; }

    for (int nb = 0; nb < ND; nb += 128) {
        float acc[4][8];
        #pragma unroll
        for (int i = 0; i < 4; i++)
            #pragma unroll
            for (int j = 0; j < 8; j++) acc[i][j] = 0.f;

        for (int k0 = 0; k0 < DP; k0 += 16) {
            {
                int row = t >> 2, kc = t & 3;
                float4 v = *(const float4*)(g_query + (size_t)(qb + row) * DP + k0 + kc * 4);
                As[kc * 4 + 0][row] = v.x; As[kc * 4 + 1][row] = v.y;
                As[kc * 4 + 2][row] = v.z; As[kc * 4 + 3][row] = v.w;
            }
            #pragma unroll
            for (int u = 0; u < 2; u++) {
                int id = t + u * 256;
                int row = id >> 2, kc = id & 3;
                float4 v = *(const float4*)(g_dict + (size_t)(nb + row) * DP + k0 + kc * 4);
                Bs[kc * 4 + 0][row] = v.x; Bs[kc * 4 + 1][row] = v.y;
                Bs[kc * 4 + 2][row] = v.z; Bs[kc * 4 + 3][row] = v.w;
            }
            __syncthreads();
            #pragma unroll
            for (int kk = 0; kk < 16; kk++) {
                float a[4], b[8];
                *(float4*)a       = *(float4*)&As[kk][ty * 4];
                *(float4*)b       = *(float4*)&Bs[kk][tx * 8];
                *(float4*)(b + 4) = *(float4*)&Bs[kk][tx * 8 + 4];
                #pragma unroll
                for (int i = 0; i < 4; i++)
                    #pragma unroll
                    for (int j = 0; j < 8; j++)
                        acc[i][j] += a[i] * b[j];
            }
            __syncthreads();
        }

        #pragma unroll
        for (int i = 0; i < 4; i++)
            #pragma unroll
            for (int j = 0; j < 8; j++)
                Ssc[ty * 4 + i][tx * 8 + j] =
                    fmaxf(acc[i][j] - g_xnh[nb + tx * 8 + j], -1e30f);
        __syncthreads();

        if (t < 64) {
            #pragma unroll 4
            for (int n = 0; n < 128; n++) {
                float s = Ssc[t][n];
                if (s > ts[CAP - 1]) {
                    ts[CAP - 1] = s; ti[CAP - 1] = nb + n;
                    #pragma unroll
                    for (int r = CAP - 1; r > 0; r--) {
                        if (ts[r] > ts[r - 1]) {
                            float tv = ts[r]; ts[r] = ts[r - 1]; ts[r - 1] = tv;
                            int   tt = ti[r]; ti[r] = ti[r - 1]; ti[r - 1] = tt;
                        }
                    }
                }
            }
        }
        __syncthreads();
    }

    if (t < 64) {
        #pragma unroll
        for (int r = 0; r < CAP; r++)
            g_cand[(size_t)(qb + t) * CAP + r] = ti[r];
    }
}

// -------- K4: refine — full reference-arithmetic emulation over 16 candidates ----
// q_norm: XLA warp-strided fp32; dot: cuBLAS-style single-acc sequential fp32 FMA
// (one lane per candidate); diss = fl32((qn + xn) - 2*dot); sort (diss asc, idx asc).
__global__ void __launch_bounds__(128) refine_kernel(float* __restrict__ out) {
    __shared__ float qs[4][DP];
    int qb = blockIdx.x * 4;
    int w = threadIdx.x >> 5;
    int lane = threadIdx.x & 31;
    int q = qb + w;

    // block-cooperative load of 4 query rows (padded zeros included)
    for (int i = threadIdx.x; i < 4 * DP / 4; i += 128) {
        int qr = i / (DP / 4), c4 = i % (DP / 4);
        *(float4*)&qs[qr][c4 * 4] =
            *(const float4*)(g_query + (size_t)(qb + qr) * DP + c4 * 4);
    }
    __syncthreads();

    // emulated q_norm (warp-strided fp32, ascending, shuffle-down tree)
    float s = 0.f;
    #pragma unroll
    for (int u = 0; u < 16; u++) {
        int j = lane + u * 32;
        if (j < DDIM) {
            float v = qs[w][j];
            s = __fadd_rn(s, __fmul_rn(v, v));
        }
    }
    #pragma unroll
    for (int o = 16; o; o >>= 1)
        s = __fadd_rn(s, __shfl_down_sync(0xffffffffu, s, o));
    float qn = __shfl_sync(0xffffffffu, s, 0);

    // per-lane candidate: sequential fp32 FMA dot over k=0..499
    float dzc = CUDART_INF_F;
    int   idxc = 0;
    if (lane < CAP) {
        idxc = g_cand[(size_t)q * CAP + lane];
        const float* drow = g_dict + (size_t)idxc * DP;
        float dot = 0.f;
        for (int k = 0; k < DDIM; k++)
            dot = __fmaf_rn(qs[w][k], drow[k], dot);
        float xn = g_xn_emu[idxc];
        float t1 = __fadd_rn(qn, xn);
        dzc = __fsub_rn(t1, __fmul_rn(2.0f, dot));
    }

    // gather to lane 0, sort 16 by (diss asc, idx asc), emit top-8
    float dz[CAP];
    int   ci[CAP];
    #pragma unroll
    for (int c = 0; c < CAP; c++) {
        dz[c] = __shfl_sync(0xffffffffu, dzc, c);
        ci[c] = __shfl_sync(0xffffffffu, idxc, c);
    }
    if (lane == 0) {
        #pragma unroll
        for (int r = 0; r < TOPK; r++) {
            int best = r;
            #pragma unroll
            for (int c = 0; c < CAP; c++) {
                if (c <= r) continue;
                if (dz[c] < dz[best] || (dz[c] == dz[best] && ci[c] < ci[best]))
                    best = c;
            }
            float td = dz[r]; dz[r] = dz[best]; dz[best] = td;
            int   tc = ci[r]; ci[r] = ci[best]; ci[best] = tc;
            out[(size_t)q * TOPK + r] = (float)ci[r];
        }
    }
}

extern "C" void kernel_launch(void* const* d_in, const int* in_sizes, int n_in,
                              void* d_out, int out_size) {
    const float* E  = nullptr;
    const float* P  = nullptr;
    const float* Dm = nullptr;
    for (int i = 0; i < n_in; i++) {
        long long sz = (long long)in_sizes[i];
        if (sz == (long long)NQ * NPIX)        E  = (const float*)d_in[i];
        else if (sz == (long long)NPIX * DDIM) P  = (const float*)d_in[i];
        else if (sz == (long long)ND * DDIM)   Dm = (const float*)d_in[i];
    }
    if (!E || !P || !Dm) {
        int idx[16];
        int m = n_in < 16 ? n_in : 16;
        for (int i = 0; i < m; i++) idx[i] = i;
        for (int a = 0; a < m; a++)
            for (int b = a + 1; b < m; b++)
                if ((long long)in_sizes[idx[b]] > (long long)in_sizes[idx[a]]) {
                    int tmp = idx[a]; idx[a] = idx[b]; idx[b] = tmp;
                }
        if (m >= 3) { Dm = (const float*)d_in[idx[0]];
                      E  = (const float*)d_in[idx[1]];
                      P  = (const float*)d_in[idx[2]]; }
    }
    if (!E || !P || !Dm) return;

    float* out = (float*)d_out;   // __output__ dtype: float32 (confirmed R7)

    static bool attr_set = false;
    if (!attr_set) {
        cudaFuncSetAttribute(queryemu_kernel,
                             cudaFuncAttributeMaxDynamicSharedMemorySize,
                             NPIX * (int)sizeof(float4));
        attr_set = true;
    }

    rowmean_kernel<<<NQ, 256>>>(E);
    dictprep_kernel<<<ND / 4, 128>>>(Dm);
    queryemu_kernel<<<NQ / 4, 512, NPIX * sizeof(float4)>>>(E, P);
    knn_kernel<<<NQ / 64, 256>>>();
    refine_kernel<<<NQ / 4, 128>>>(out);
}

// round 13
// speedup vs baseline: 6.1561x; 6.1561x over previous
#include <cuda_runtime.h>
#include <cuda_bf16.h>
#include <math_constants.h>
#include <cstdint>

#define NQ   16384
#define NPIX 3600
#define ND   131072
#define DDIM 500
#define DP   512   // padded K
#define TOPK 8
#define CAP  16

// ---------------- scratch (__device__ globals; no allocation) ----------------
__device__ float          g_query[(size_t)NQ * DP];   // emulated ref query (f32)
__device__ float          g_dict[(size_t)ND * DP];    // f32 dict, zero-padded
__device__ __nv_bfloat16  g_qbf[(size_t)NQ * DP];     // bf16 query (pass-1)
__device__ __nv_bfloat16  g_dbf[(size_t)ND * DP];     // bf16 dict  (pass-1)
__device__ float          g_xn_emu[ND];               // emulated fp32 ||d||^2
__device__ float          g_xnh[ND];                  // 0.5*||d||^2 (pass-1)
__device__ float          g_mean32[NQ];
__device__ int            g_cand[(size_t)NQ * CAP];

__device__ __forceinline__ uint32_t s2u(const void* p) {
    uint32_t a;
    asm("{ .reg .u64 t; cvta.to.shared.u64 t, %1; cvt.u32.u64 %0, t; }"
        : "=r"(a) : "l"(p));
    return a;
}

#define LDMATRIX_X4(r, addr)                                                   \
    asm volatile("ldmatrix.sync.aligned.m8n8.x4.shared.b16 {%0,%1,%2,%3}, [%4];" \
        : "=r"((r)[0]), "=r"((r)[1]), "=r"((r)[2]), "=r"((r)[3]) : "r"(addr))
#define MMA16816(d, a, b)                                                      \
    asm volatile("mma.sync.aligned.m16n8k16.row.col.f32.bf16.bf16.f32 "        \
        "{%0,%1,%2,%3}, {%4,%5,%6,%7}, {%8,%9}, {%0,%1,%2,%3};"                \
        : "+f"((d)[0]), "+f"((d)[1]), "+f"((d)[2]), "+f"((d)[3])               \
        : "r"((a)[0]), "r"((a)[1]), "r"((a)[2]), "r"((a)[3]),                  \
          "r"((b)[0]), "r"((b)[1]))

// ---------------- K0: row means (fp64) ----------------
__global__ void rowmean_kernel(const float* __restrict__ E) {
    int row = blockIdx.x;
    const float* r = E + (size_t)row * NPIX;
    double s = 0.0;
    for (int i = threadIdx.x; i < NPIX; i += 256) s += (double)r[i];
    __shared__ double sh[8];
    #pragma unroll
    for (int o = 16; o; o >>= 1) s += __shfl_down_sync(0xffffffffu, s, o);
    if ((threadIdx.x & 31) == 0) sh[threadIdx.x >> 5] = s;
    __syncthreads();
    if (threadIdx.x == 0) {
        double t = 0.0;
        #pragma unroll
        for (int w = 0; w < 8; w++) t += sh[w];
        g_mean32[row] = __fdiv_rn((float)t, (float)NPIX);
    }
}

// ---------------- K1: dict prep: f32 pad + bf16 + emulated norms ----------------
__global__ void dictprep_kernel(const float* __restrict__ Dm) {
    int row = blockIdx.x * 4 + (threadIdx.x >> 5);
    int lane = threadIdx.x & 31;
    const float* src = Dm + (size_t)row * DDIM;
    float* dst = g_dict + (size_t)row * DP;
    __nv_bfloat16* dbf = g_dbf + (size_t)row * DP;
    float s = 0.f;
    #pragma unroll
    for (int u = 0; u < 16; u++) {
        int j = lane + u * 32;
        float v = (j < DDIM) ? src[j] : 0.f;
        dst[j] = v;
        dbf[j] = __float2bfloat16(v);
        if (j < DDIM) s = __fadd_rn(s, __fmul_rn(v, v));
    }
    #pragma unroll
    for (int o = 16; o; o >>= 1)
        s = __fadd_rn(s, __shfl_down_sync(0xffffffffu, s, o));
    if (lane == 0) {
        g_xn_emu[row] = s;
        g_xnh[row] = 0.5f * s;
    }
}

// ---- K2: emulated query GEMM, 8 queries/block (per-(q,j) order = cuBLAS seq-k) ----
__global__ void __launch_bounds__(512) queryemu_kernel(const float* __restrict__ E,
                                                       const float* __restrict__ P) {
    extern __shared__ float cs[];   // [NPIX][8] centered values
    int qb = blockIdx.x * 8;
    int t = threadIdx.x;
    float m[8];
    #pragma unroll
    for (int q = 0; q < 8; q++) m[q] = g_mean32[qb + q];
    for (int k = t; k < NPIX; k += 512) {
        #pragma unroll
        for (int q = 0; q < 8; q++)
            cs[k * 8 + q] = __fsub_rn(E[(size_t)(qb + q) * NPIX + k], m[q]);
    }
    __syncthreads();
    if (t < DDIM) {
        float a[8] = {};
        const float* p = P + t;
        for (int k = 0; k < NPIX; k++) {
            float pv = p[(size_t)k * DDIM];
            #pragma unroll
            for (int q = 0; q < 8; q++)
                a[q] = __fmaf_rn(cs[k * 8 + q], pv, a[q]);
        }
        #pragma unroll
        for (int q = 0; q < 8; q++)
            g_query[(size_t)(qb + q) * DP + t] = a[q];
    } else {
        #pragma unroll
        for (int q = 0; q < 8; q++)
            g_query[(size_t)(qb + q) * DP + t] = 0.f;
    }
}

// ---------------- K3: query f32 -> bf16 ----------------
__global__ void qbf_kernel() {
    size_t i = (size_t)blockIdx.x * blockDim.x + threadIdx.x;
    if (i < (size_t)NQ * DP) g_qbf[i] = __float2bfloat16(g_query[i]);
}

// ------------- K4: HMMA (mma.sync bf16) pass-1: scores + top-16 capture -------------
// 128 CTAs x 256 thr (8 warps: wm=w/4 in [0,2), wn=w%4 in [0,4)).
// A: [128 q][512 k] bf16 smem, XOR-swizzled 16B chunks (chunk' = c ^ (row&7)).
// B: double-buffered [128 n][128 k] bf16 chunks, stored [n][k] = col-major KxN
//    => ldmatrix WITHOUT trans yields the required B fragment. acc: 64x32/warp.
#define SA    0
#define SB    131072                 // 2 x 32768
#define SS    (131072 + 65536)       // scores 128 x 65 f32
#define SX    (SS + 128 * 65 * 4)    // xnh 128 f32
#define SMEM_KNN (SX + 512)

__global__ void __launch_bounds__(256) knn_mma() {
    extern __shared__ char sm[];
    float* Ssc  = (float*)(sm + SS);
    float* sxnh = (float*)(sm + SX);
    uint32_t sbase = s2u(sm);
    int tid = threadIdx.x;
    int w = tid >> 5, l = tid & 31;
    int wm = w >> 2, wn = w & 3;
    int qb = blockIdx.x * 128;

    // Load A (queries) with swizzle: 8192 16B-chunks
    {
        const uint4* src = (const uint4*)(g_qbf + (size_t)qb * DP);
        #pragma unroll 4
        for (int i = 0; i < 32; i++) {
            int idx = i * 256 + tid;
            int r = idx >> 6, c = idx & 63;
            uint4 v = src[(size_t)r * 64 + c];
            *(uint4*)(sm + SA + (((r << 6) + (c ^ (r & 7))) << 4)) = v;
        }
    }

    float ts[CAP];
    int   ti[CAP];
    #pragma unroll
    for (int r = 0; r < CAP; r++) { ts[r] = -CUDART_INF_F; ti[r] = 0; }

    int srow = tid & 127, shalf = tid >> 7;   // scanner: 2 threads per query row

    for (int t = 0; t < ND / 128; t++) {
        int nb = t * 128;
        if (tid < 128) sxnh[tid] = g_xnh[nb + tid];

        const uint4* dsrc = (const uint4*)(g_dbf + (size_t)nb * DP);
        uint4 pre[8];
        // chunk 0 -> buf 0
        #pragma unroll
        for (int i = 0; i < 8; i++) {
            int idx = i * 256 + tid;
            int r = idx >> 4, c = idx & 15;
            pre[i] = dsrc[(size_t)(r << 6) + c];
        }
        #pragma unroll
        for (int i = 0; i < 8; i++) {
            int idx = i * 256 + tid;
            int r = idx >> 4, c = idx & 15;
            *(uint4*)(sm + SB + (((r << 4) + (c ^ (r & 7))) << 4)) = pre[i];
        }
        __syncthreads();

        float acc[4][4][4];
        #pragma unroll
        for (int mt = 0; mt < 4; mt++)
            #pragma unroll
            for (int nt = 0; nt < 4; nt++)
                #pragma unroll
                for (int rr = 0; rr < 4; rr++) acc[mt][nt][rr] = 0.f;

        #pragma unroll
        for (int kc = 0; kc < 4; kc++) {
            if (kc < 3) {
                #pragma unroll
                for (int i = 0; i < 8; i++) {
                    int idx = i * 256 + tid;
                    int r = idx >> 4, c = idx & 15;
                    pre[i] = dsrc[(size_t)(r << 6) + ((kc + 1) << 4) + c];
                }
            }
            uint32_t Bcur = sbase + SB + (kc & 1) * 32768;
            #pragma unroll
            for (int ks = 0; ks < 8; ks++) {
                uint32_t a[4][4], b[4][2];
                #pragma unroll
                for (int mt = 0; mt < 4; mt++) {
                    int r = wm * 64 + mt * 16 + (l & 15);
                    int c = kc * 16 + ks * 2 + (l >> 4);
                    uint32_t ad = sbase + SA + (((r << 6) + (c ^ (r & 7))) << 4);
                    LDMATRIX_X4(a[mt], ad);
                }
                #pragma unroll
                for (int p2 = 0; p2 < 2; p2++) {
                    // tiles: (n0-7,k0-7),(n0-7,k8-15),(n8-15,k0-7),(n8-15,k8-15)
                    int n = wn * 32 + p2 * 16 + ((l >> 4) & 1) * 8 + (l & 7);
                    int c = ks * 2 + ((l >> 3) & 1);
                    uint32_t ad = Bcur + (((n << 4) + (c ^ (n & 7))) << 4);
                    uint32_t r4[4];
                    LDMATRIX_X4(r4, ad);     // NON-trans: [n][k] is col-major KxN
                    b[p2 * 2 + 0][0] = r4[0]; b[p2 * 2 + 0][1] = r4[1];
                    b[p2 * 2 + 1][0] = r4[2]; b[p2 * 2 + 1][1] = r4[3];
                }
                #pragma unroll
                for (int mt = 0; mt < 4; mt++)
                    #pragma unroll
                    for (int nt = 0; nt < 4; nt++)
                        MMA16816(acc[mt][nt], a[mt], b[nt]);
            }
            __syncthreads();              // all reads of Bcur done
            if (kc < 3) {
                #pragma unroll
                for (int i = 0; i < 8; i++) {
                    int idx = i * 256 + tid;
                    int r = idx >> 4, c = idx & 15;
                    *(uint4*)(sm + SB + ((kc + 1) & 1) * 32768 +
                              (((r << 4) + (c ^ (r & 7))) << 4)) = pre[i];
                }
                __syncthreads();
            }
        }

        // Epilogue: two n-half passes through the 128x65 score pane
        #pragma unroll
        for (int p = 0; p < 2; p++) {
            if ((wn >> 1) == p) {
                int nloc = (wn & 1) * 32;
                #pragma unroll
                for (int mt = 0; mt < 4; mt++)
                    #pragma unroll
                    for (int nt = 0; nt < 4; nt++) {
                        int r = wm * 64 + mt * 16 + (l >> 2);
                        int cb = nloc + nt * 8 + (l & 3) * 2;
                        int gc = p * 64 + cb;
                        Ssc[r * 65 + cb]           = acc[mt][nt][0] - sxnh[gc];
                        Ssc[r * 65 + cb + 1]       = acc[mt][nt][1] - sxnh[gc + 1];
                        Ssc[(r + 8) * 65 + cb]     = acc[mt][nt][2] - sxnh[gc];
                        Ssc[(r + 8) * 65 + cb + 1] = acc[mt][nt][3] - sxnh[gc + 1];
                    }
            }
            __syncthreads();
            int cb = shalf * 32;
            #pragma unroll 8
            for (int cc = 0; cc < 32; cc++) {
                float s = Ssc[srow * 65 + cb + cc];
                if (s > ts[CAP - 1]) {
                    ts[CAP - 1] = s; ti[CAP - 1] = nb + p * 64 + cb + cc;
                    #pragma unroll
                    for (int r = CAP - 1; r > 0; r--) {
                        if (ts[r] > ts[r - 1]) {
                            float tv = ts[r]; ts[r] = ts[r - 1]; ts[r - 1] = tv;
                            int   tt = ti[r]; ti[r] = ti[r - 1]; ti[r - 1] = tt;
                        }
                    }
                }
            }
            __syncthreads();
        }
    }

    // Final merge: two sorted-desc lists per row -> top-16 -> g_cand
    float* msc = Ssc;                  // reuse score pane
    int*   mix = (int*)(sm + SB);
    #pragma unroll
    for (int r = 0; r < CAP; r++) { msc[tid * CAP + r] = ts[r]; mix[tid * CAP + r] = ti[r]; }
    __syncthreads();
    if (tid < 128) {
        int i0 = 0, i1 = 0;
        #pragma unroll
        for (int r = 0; r < CAP; r++) {
            float s0 = msc[tid * CAP + i0];
            float s1 = msc[(tid + 128) * CAP + i1];
            bool take0 = (s0 >= s1);
            int idx = take0 ? mix[tid * CAP + i0] : mix[(tid + 128) * CAP + i1];
            g_cand[(size_t)(qb + tid) * CAP + r] = idx;
            if (take0) i0++; else i1++;
        }
    }
}

// -------- K5: refine — reference-arithmetic emulation over 16 candidates ----
__global__ void __launch_bounds__(128) refine_kernel(float* __restrict__ out) {
    __shared__ float qs[4][DP];
    int qb = blockIdx.x * 4;
    int w = threadIdx.x >> 5;
    int lane = threadIdx.x & 31;
    int q = qb + w;

    for (int i = threadIdx.x; i < 4 * DP / 4; i += 128) {
        int qr = i / (DP / 4), c4 = i % (DP / 4);
        *(float4*)&qs[qr][c4 * 4] =
            *(const float4*)(g_query + (size_t)(qb + qr) * DP + c4 * 4);
    }
    __syncthreads();

    float s = 0.f;
    #pragma unroll
    for (int u = 0; u < 16; u++) {
        int j = lane + u * 32;
        if (j < DDIM) {
            float v = qs[w][j];
            s = __fadd_rn(s, __fmul_rn(v, v));
        }
    }
    #pragma unroll
    for (int o = 16; o; o >>= 1)
        s = __fadd_rn(s, __shfl_down_sync(0xffffffffu, s, o));
    float qn = __shfl_sync(0xffffffffu, s, 0);

    float dzc = CUDART_INF_F;
    int   idxc = 0;
    if (lane < CAP) {
        idxc = g_cand[(size_t)q * CAP + lane];
        const float* drow = g_dict + (size_t)idxc * DP;
        float dot = 0.f;
        for (int k = 0; k < DDIM; k++)
            dot = __fmaf_rn(qs[w][k], drow[k], dot);
        float xn = g_xn_emu[idxc];
        float t1 = __fadd_rn(qn, xn);
        dzc = __fsub_rn(t1, __fmul_rn(2.0f, dot));
    }

    float dz[CAP];
    int   ci[CAP];
    #pragma unroll
    for (int c = 0; c < CAP; c++) {
        dz[c] = __shfl_sync(0xffffffffu, dzc, c);
        ci[c] = __shfl_sync(0xffffffffu, idxc, c);
    }
    if (lane == 0) {
        #pragma unroll
        for (int r = 0; r < TOPK; r++) {
            int best = r;
            #pragma unroll
            for (int c = 0; c < CAP; c++) {
                if (c <= r) continue;
                if (dz[c] < dz[best] || (dz[c] == dz[best] && ci[c] < ci[best]))
                    best = c;
            }
            float td = dz[r]; dz[r] = dz[best]; dz[best] = td;
            int   tc = ci[r]; ci[r] = ci[best]; ci[best] = tc;
            out[(size_t)q * TOPK + r] = (float)ci[r];
        }
    }
}

extern "C" void kernel_launch(void* const* d_in, const int* in_sizes, int n_in,
                              void* d_out, int out_size) {
    const float* E  = nullptr;
    const float* P  = nullptr;
    const float* Dm = nullptr;
    for (int i = 0; i < n_in; i++) {
        long long sz = (long long)in_sizes[i];
        if (sz == (long long)NQ * NPIX)        E  = (const float*)d_in[i];
        else if (sz == (long long)NPIX * DDIM) P  = (const float*)d_in[i];
        else if (sz == (long long)ND * DDIM)   Dm = (const float*)d_in[i];
    }
    if (!E || !P || !Dm) {
        int idx[16];
        int m = n_in < 16 ? n_in : 16;
        for (int i = 0; i < m; i++) idx[i] = i;
        for (int a = 0; a < m; a++)
            for (int b = a + 1; b < m; b++)
                if ((long long)in_sizes[idx[b]] > (long long)in_sizes[idx[a]]) {
                    int tmp = idx[a]; idx[a] = idx[b]; idx[b] = tmp;
                }
        if (m >= 3) { Dm = (const float*)d_in[idx[0]];
                      E  = (const float*)d_in[idx[1]];
                      P  = (const float*)d_in[idx[2]]; }
    }
    if (!E || !P || !Dm) return;

    float* out = (float*)d_out;

    static bool attr_set = false;
    if (!attr_set) {
        cudaFuncSetAttribute(queryemu_kernel,
                             cudaFuncAttributeMaxDynamicSharedMemorySize,
                             NPIX * 8 * (int)sizeof(float));
        cudaFuncSetAttribute(knn_mma,
                             cudaFuncAttributeMaxDynamicSharedMemorySize,
                             SMEM_KNN);
        attr_set = true;
    }

    rowmean_kernel<<<NQ, 256>>>(E);
    dictprep_kernel<<<ND / 4, 128>>>(Dm);
    queryemu_kernel<<<NQ / 8, 512, NPIX * 8 * sizeof(float)>>>(E, P);
    qbf_kernel<<<(int)(((size_t)NQ * DP + 255) / 256), 256>>>();
    knn_mma<<<NQ / 128, 256, SMEM_KNN>>>();
    refine_kernel<<<NQ / 4, 128>>>(out);
}